// round 3
// baseline (speedup 1.0000x reference)
#include <cuda_runtime.h>

// Problem constants
#define BATCH   4
#define NQ      1024
#define NJ      2048
#define DMODEL  768
#define HEADS   12
#define DHEAD   64
#define INNER   768
#define SCALE   0.125f

// ---------------------------------------------------------------------------
// Scratch
// ---------------------------------------------------------------------------
__device__ float g_q  [BATCH * NQ * INNER];
__device__ float g_kv [BATCH * NJ * 2 * INNER];
__device__ float g_dots[(size_t)BATCH * NQ * HEADS * NJ];
__device__ float g_ao [BATCH * NQ * INNER];

struct GemmParams {
    const float* A;
    const float* A2;
    const float* B;
    float*       C;
    const float* bias;
    int M, N, K;
    int lda, ldb, ldc;
    int Z2;
    long as1, as2, bs1, bs2, cs1, cs2;
    float alpha;
    int gatherSplit;
};

__device__ __forceinline__ float f2tf(float x) {
    unsigned u;
    asm("cvt.rna.tf32.f32 %0, %1;" : "=r"(u) : "f"(x));
    return __uint_as_float(u);
}

__device__ __forceinline__ void mma_tf32(float* c, const float* a, float b0, float b1) {
    asm volatile(
        "mma.sync.aligned.m16n8k8.row.col.f32.tf32.tf32.f32 "
        "{%0,%1,%2,%3},{%4,%5,%6,%7},{%8,%9},{%0,%1,%2,%3};"
        : "+f"(c[0]), "+f"(c[1]), "+f"(c[2]), "+f"(c[3])
        : "r"(__float_as_uint(a[0])), "r"(__float_as_uint(a[1])),
          "r"(__float_as_uint(a[2])), "r"(__float_as_uint(a[3])),
          "r"(__float_as_uint(b0)),  "r"(__float_as_uint(b1)));
}

// k-dependent XOR swizzle on the m/n index (keeps STS and LDS conflicts <=2-way)
__device__ __forceinline__ int sw(int k, int m) { return m ^ ((k & 12) >> 1); }

// ---------------------------------------------------------------------------
// Double-buffered 3xTF32 tensor-core GEMM (fp32-accurate).
// smem holds {hi,lo} interleaved float2; producer prefetches slab s+1 into
// registers while MMAs consume slab s.  One __syncthreads per slab.
//   A: [M,K] row-major (optional 2-source row gather)
//   B: BT=false -> [K,N] row-major;  BT=true -> [N,K] row-major
// ---------------------------------------------------------------------------
template<int BM, int BN, int BK, int WM, int WN, bool BT, bool GATHER>
__global__ void __launch_bounds__((BM/WM)*(BN/WN)*32, 2) mma_gemm(GemmParams p) {
    constexpr int WARPS_M = BM / WM;
    constexpr int WARPS_N = BN / WN;
    constexpr int THREADS = WARPS_M * WARPS_N * 32;
    constexpr int MT  = WM / 16;
    constexpr int NTL = WN / 8;
    constexpr int KS  = BK / 8;
    constexpr int LDA2 = BM + 4;   // float2 stride per k-row
    constexpr int LDB2 = BN + 4;
    constexpr int A_F4 = BM * BK / 4 / THREADS;
    constexpr int B_F4 = BN * BK / 4 / THREADS;

    extern __shared__ float2 smem[];
    float2* Abuf[2] = { smem, smem + BK * LDA2 };
    float2* Bbuf[2] = { smem + 2 * BK * LDA2, smem + 2 * BK * LDA2 + BK * LDB2 };

    const int z  = blockIdx.z;
    const int z1 = z / p.Z2;
    const int z2 = z - z1 * p.Z2;
    const float* A  = p.A + z1 * p.as1 + z2 * p.as2;
    const float* A2 = GATHER ? (p.A2 + z1 * p.as1) : nullptr;
    const float* B  = p.B + z1 * p.bs1 + z2 * p.bs2;
    float*       C  = p.C + z1 * p.cs1 + z2 * p.cs2;

    const int m0 = blockIdx.y * BM;
    const int n0 = blockIdx.x * BN;
    const int tid  = threadIdx.x;
    const int wid  = tid >> 5;
    const int lane = tid & 31;
    const int wm = wid % WARPS_M;
    const int wn = wid / WARPS_M;
    const int g = lane >> 2;
    const int t = lane & 3;

    float acc[MT][NTL][4];
#pragma unroll
    for (int mi = 0; mi < MT; mi++)
#pragma unroll
        for (int ni = 0; ni < NTL; ni++)
#pragma unroll
            for (int e = 0; e < 4; e++) acc[mi][ni][e] = 0.0f;

    float4 ra[A_F4], rb[B_F4];

    // ---- stage loaders (global -> regs) ----
    auto loadA = [&](int k0) {
#pragma unroll
        for (int i = 0; i < A_F4; i++) {
            int it  = tid + i * THREADS;
            int row = it / (BK / 4);
            int c4  = (it % (BK / 4)) * 4;
            const float* ap;
            if (GATHER) {
                int m = m0 + row;
                ap = (m < p.gatherSplit)
                         ? (A  + (long)m * p.lda)
                         : (A2 + (long)(m - p.gatherSplit) * p.lda);
            } else {
                ap = A + (long)(m0 + row) * p.lda;
            }
            ra[i] = *(const float4*)(ap + k0 + c4);
        }
    };
    auto loadB = [&](int k0) {
#pragma unroll
        for (int i = 0; i < B_F4; i++) {
            int it = tid + i * THREADS;
            if (BT) {
                int row = it / (BK / 4);
                int c4  = (it % (BK / 4)) * 4;
                rb[i] = *(const float4*)(B + (long)(n0 + row) * p.ldb + k0 + c4);
            } else {
                int row = it / (BN / 4);
                int c4  = (it % (BN / 4)) * 4;
                rb[i] = *(const float4*)(B + (long)(k0 + row) * p.ldb + n0 + c4);
            }
        }
    };
    // ---- stage storers (regs -> smem, tf32 hi/lo split) ----
    auto storeA = [&](int buf) {
        float2* As = Abuf[buf];
#pragma unroll
        for (int i = 0; i < A_F4; i++) {
            int it  = tid + i * THREADS;
            int row = it / (BK / 4);
            int c4  = (it % (BK / 4)) * 4;
            float vv[4] = {ra[i].x, ra[i].y, ra[i].z, ra[i].w};
#pragma unroll
            for (int e = 0; e < 4; e++) {
                int k = c4 + e;
                float hi = f2tf(vv[e]);
                As[k * LDA2 + sw(k, row)] = make_float2(hi, f2tf(vv[e] - hi));
            }
        }
    };
    auto storeB = [&](int buf) {
        float2* Bs = Bbuf[buf];
#pragma unroll
        for (int i = 0; i < B_F4; i++) {
            int it = tid + i * THREADS;
            float vv[4] = {rb[i].x, rb[i].y, rb[i].z, rb[i].w};
            if (BT) {
                int row = it / (BK / 4);
                int c4  = (it % (BK / 4)) * 4;
#pragma unroll
                for (int e = 0; e < 4; e++) {
                    int k = c4 + e;
                    float hi = f2tf(vv[e]);
                    Bs[k * LDB2 + sw(k, row)] = make_float2(hi, f2tf(vv[e] - hi));
                }
            } else {
                int row = it / (BN / 4);
                int c4  = (it % (BN / 4)) * 4;
#pragma unroll
                for (int e = 0; e < 4; e++) {
                    int n = c4 + e;
                    float hi = f2tf(vv[e]);
                    Bs[row * LDB2 + sw(row, n)] = make_float2(hi, f2tf(vv[e] - hi));
                }
            }
        }
    };

    const int S = p.K / BK;
    loadA(0); loadB(0);
    storeA(0); storeB(0);
    __syncthreads();

    for (int s = 0; s < S; s++) {
        if (s + 1 < S) { loadA((s + 1) * BK); loadB((s + 1) * BK); }

        const float2* As = Abuf[s & 1];
        const float2* Bs = Bbuf[s & 1];
#pragma unroll
        for (int ks = 0; ks < KS; ks++) {
            const int kb  = ks * 8;
            const int kr0 = kb + t;
            const int kr1 = kb + t + 4;
            const int s0  = (kr0 & 12) >> 1;
            const int s1  = (kr1 & 12) >> 1;

            float2 af[MT][4];
#pragma unroll
            for (int mi = 0; mi < MT; mi++) {
                int rb0 = wm * WM + mi * 16;
                af[mi][0] = As[kr0 * LDA2 + ((rb0 + g)     ^ s0)];
                af[mi][1] = As[kr0 * LDA2 + ((rb0 + g + 8) ^ s0)];
                af[mi][2] = As[kr1 * LDA2 + ((rb0 + g)     ^ s1)];
                af[mi][3] = As[kr1 * LDA2 + ((rb0 + g + 8) ^ s1)];
            }
#pragma unroll
            for (int ni = 0; ni < NTL; ni++) {
                int cb = wn * WN + ni * 8 + g;
                float2 b0 = Bs[kr0 * LDB2 + (cb ^ s0)];
                float2 b1 = Bs[kr1 * LDB2 + (cb ^ s1)];
#pragma unroll
                for (int mi = 0; mi < MT; mi++) {
                    float ah[4] = {af[mi][0].x, af[mi][1].x, af[mi][2].x, af[mi][3].x};
                    float al[4] = {af[mi][0].y, af[mi][1].y, af[mi][2].y, af[mi][3].y};
                    mma_tf32(acc[mi][ni], ah, b0.x, b1.x);  // hi*hi
                    mma_tf32(acc[mi][ni], ah, b0.y, b1.y);  // hi*lo
                    mma_tf32(acc[mi][ni], al, b0.x, b1.x);  // lo*hi
                }
            }
        }

        if (s + 1 < S) { storeA((s + 1) & 1); storeB((s + 1) & 1); }
        __syncthreads();
    }

    // ---- epilogue ----
#pragma unroll
    for (int mi = 0; mi < MT; mi++) {
        int r0 = m0 + wm * WM + mi * 16 + g;
#pragma unroll
        for (int ni = 0; ni < NTL; ni++) {
            int col = n0 + wn * WN + ni * 8 + t * 2;
            float bx = 0.f, by = 0.f;
            if (p.bias) { bx = p.bias[col]; by = p.bias[col + 1]; }
            float2 v0, v1;
            v0.x = acc[mi][ni][0] * p.alpha + bx;
            v0.y = acc[mi][ni][1] * p.alpha + by;
            v1.x = acc[mi][ni][2] * p.alpha + bx;
            v1.y = acc[mi][ni][3] * p.alpha + by;
            *(float2*)&C[(long)r0 * p.ldc + col]       = v0;
            *(float2*)&C[(long)(r0 + 8) * p.ldc + col] = v1;
        }
    }
}

// ---------------------------------------------------------------------------
// Register-resident talking-heads: pre-mix -> softmax -> post-mix, in-place.
// ---------------------------------------------------------------------------
__global__ void __launch_bounds__(512) mix_softmax2(
    float* __restrict__ dots,
    const float* __restrict__ pre_g,
    const float* __restrict__ post_g)
{
    __shared__ float s_pre[HEADS * HEADS], s_post[HEADS * HEADS];
    __shared__ float red[16][HEADS];
    __shared__ float bm[HEADS], bs[HEADS];

    const int tid = threadIdx.x;
    if (tid < HEADS * HEADS) { s_pre[tid] = pre_g[tid]; s_post[tid] = post_g[tid]; }
    __syncthreads();

    const long base = (long)blockIdx.x * (HEADS * NJ);
    const int j0 = tid * 4;
    const int w = tid >> 5, lane = tid & 31;

    float4 mx[HEADS];
#pragma unroll
    for (int gg = 0; gg < HEADS; gg++) mx[gg] = make_float4(0.f, 0.f, 0.f, 0.f);
#pragma unroll
    for (int h = 0; h < HEADS; h++) {
        float4 r = *(const float4*)(dots + base + (long)h * NJ + j0);
#pragma unroll
        for (int gg = 0; gg < HEADS; gg++) {
            float wv = s_pre[h * HEADS + gg];
            mx[gg].x += r.x * wv;
            mx[gg].y += r.y * wv;
            mx[gg].z += r.z * wv;
            mx[gg].w += r.w * wv;
        }
    }

    float m[HEADS];
#pragma unroll
    for (int gg = 0; gg < HEADS; gg++)
        m[gg] = fmaxf(fmaxf(mx[gg].x, mx[gg].y), fmaxf(mx[gg].z, mx[gg].w));
#pragma unroll
    for (int gg = 0; gg < HEADS; gg++)
#pragma unroll
        for (int o = 16; o; o >>= 1)
            m[gg] = fmaxf(m[gg], __shfl_xor_sync(0xFFFFFFFFu, m[gg], o));
#pragma unroll
    for (int gg = 0; gg < HEADS; gg++)
        if (lane == gg) red[w][gg] = m[gg];
    __syncthreads();
    if (tid < HEADS) {
        float mm = -1e30f;
#pragma unroll
        for (int ww = 0; ww < 16; ww++) mm = fmaxf(mm, red[ww][tid]);
        bm[tid] = mm;
    }
    __syncthreads();

    float s[HEADS];
#pragma unroll
    for (int gg = 0; gg < HEADS; gg++) {
        float mm = bm[gg];
        mx[gg].x = __expf(mx[gg].x - mm);
        mx[gg].y = __expf(mx[gg].y - mm);
        mx[gg].z = __expf(mx[gg].z - mm);
        mx[gg].w = __expf(mx[gg].w - mm);
        s[gg] = (mx[gg].x + mx[gg].y) + (mx[gg].z + mx[gg].w);
    }
#pragma unroll
    for (int gg = 0; gg < HEADS; gg++)
#pragma unroll
        for (int o = 16; o; o >>= 1)
            s[gg] += __shfl_xor_sync(0xFFFFFFFFu, s[gg], o);
    __syncthreads();
#pragma unroll
    for (int gg = 0; gg < HEADS; gg++)
        if (lane == gg) red[w][gg] = s[gg];
    __syncthreads();
    if (tid < HEADS) {
        float ss = 0.f;
#pragma unroll
        for (int ww = 0; ww < 16; ww++) ss += red[ww][tid];
        bs[tid] = ss;
    }
    __syncthreads();

#pragma unroll
    for (int gg = 0; gg < HEADS; gg++) {
        float inv = 1.0f / bs[gg];
        mx[gg].x *= inv; mx[gg].y *= inv; mx[gg].z *= inv; mx[gg].w *= inv;
    }

#pragma unroll
    for (int gg = 0; gg < HEADS; gg++) {
        float4 o = make_float4(0.f, 0.f, 0.f, 0.f);
#pragma unroll
        for (int h = 0; h < HEADS; h++) {
            float wv = s_post[h * HEADS + gg];
            o.x += mx[h].x * wv;
            o.y += mx[h].y * wv;
            o.z += mx[h].z * wv;
            o.w += mx[h].w * wv;
        }
        *(float4*)(dots + base + (long)gg * NJ + j0) = o;
    }
}

// ---------------------------------------------------------------------------
// Launch
// ---------------------------------------------------------------------------
#define SMEM_BIG  ((2*16*(128+4) + 2*16*(128+4)) * 8)   // 67584 B (128x128 cfg)
#define SMEM_K5   ((2*16*(128+4) + 2*16*(64+4)) * 8)    // 51200 B (128x64 cfg)

extern "C" void kernel_launch(void* const* d_in, const int* in_sizes, int n_in,
                              void* d_out, int out_size) {
    (void)in_sizes; (void)n_in; (void)out_size;
    const float* x        = (const float*)d_in[0];
    const float* context  = (const float*)d_in[1];
    const float* Wq       = (const float*)d_in[2];
    const float* Wkv      = (const float*)d_in[3];
    const float* mix_pre  = (const float*)d_in[4];
    const float* mix_post = (const float*)d_in[5];
    const float* Wout     = (const float*)d_in[6];
    const float* b_out    = (const float*)d_in[7];
    float* out = (float*)d_out;

    float *q, *kv, *dots, *ao;
    cudaGetSymbolAddress((void**)&q,    g_q);
    cudaGetSymbolAddress((void**)&kv,   g_kv);
    cudaGetSymbolAddress((void**)&dots, g_dots);
    cudaGetSymbolAddress((void**)&ao,   g_ao);

    const long Q_B  = (long)NQ * INNER;
    const long KV_B = (long)NJ * 2 * INNER;
    const long D_B  = (long)NQ * HEADS * NJ;

    cudaFuncSetAttribute((const void*)mma_gemm<128,128,16,64,64,false,false>,
                         cudaFuncAttributeMaxDynamicSharedMemorySize, SMEM_BIG);
    cudaFuncSetAttribute((const void*)mma_gemm<128,128,16,64,64,false,true>,
                         cudaFuncAttributeMaxDynamicSharedMemorySize, SMEM_BIG);
    cudaFuncSetAttribute((const void*)mma_gemm<128,128,16,64,64,true,false>,
                         cudaFuncAttributeMaxDynamicSharedMemorySize, SMEM_BIG);
    cudaFuncSetAttribute((const void*)mma_gemm<128,64,16,64,32,false,false>,
                         cudaFuncAttributeMaxDynamicSharedMemorySize, SMEM_K5);

    // K1: q = x @ Wq
    {
        GemmParams p = {};
        p.A = x; p.B = Wq; p.C = q;
        p.M = BATCH * NQ; p.N = INNER; p.K = DMODEL;
        p.lda = DMODEL; p.ldb = INNER; p.ldc = INNER;
        p.Z2 = 1; p.alpha = 1.0f;
        mma_gemm<128,128,16,64,64,false,false>
            <<<dim3(INNER/128, BATCH*NQ/128, 1), 128, SMEM_BIG>>>(p);
    }
    // K2: kv = concat(x, context) @ Wkv
    {
        GemmParams p = {};
        p.A = x; p.A2 = context; p.B = Wkv; p.C = kv;
        p.M = NJ; p.N = 2 * INNER; p.K = DMODEL;
        p.lda = DMODEL; p.ldb = 2 * INNER; p.ldc = 2 * INNER;
        p.Z2 = 1; p.as1 = (long)NQ * DMODEL; p.cs1 = KV_B;
        p.alpha = 1.0f; p.gatherSplit = NQ;
        mma_gemm<128,128,16,64,64,false,true>
            <<<dim3(2*INNER/128, NJ/128, BATCH), 128, SMEM_BIG>>>(p);
    }
    // K3: dots = SCALE * q @ k^T   (NT, 48 batch-heads)
    {
        GemmParams p = {};
        p.A = q; p.B = kv; p.C = dots;
        p.M = NQ; p.N = NJ; p.K = DHEAD;
        p.lda = INNER; p.ldb = 2 * INNER; p.ldc = HEADS * NJ;
        p.Z2 = HEADS;
        p.as1 = Q_B;  p.as2 = DHEAD;
        p.bs1 = KV_B; p.bs2 = DHEAD;
        p.cs1 = D_B;  p.cs2 = NJ;
        p.alpha = SCALE;
        mma_gemm<128,128,16,64,64,true,false>
            <<<dim3(NJ/128, NQ/128, BATCH*HEADS), 128, SMEM_BIG>>>(p);
    }
    // K4: fused talking-heads softmax
    mix_softmax2<<<BATCH * NQ, 512>>>(dots, mix_pre, mix_post);
    // K5: ao = attn @ v   (NN, 48 batch-heads)
    {
        GemmParams p = {};
        p.A = dots; p.B = kv + INNER; p.C = ao;
        p.M = NQ; p.N = DHEAD; p.K = NJ;
        p.lda = HEADS * NJ; p.ldb = 2 * INNER; p.ldc = INNER;
        p.Z2 = HEADS;
        p.as1 = D_B;  p.as2 = NJ;
        p.bs1 = KV_B; p.bs2 = DHEAD;
        p.cs1 = Q_B;  p.cs2 = DHEAD;
        p.alpha = 1.0f;
        mma_gemm<128,64,16,64,32,false,false>
            <<<dim3(1, NQ/128, BATCH*HEADS), 128, SMEM_K5>>>(p);
    }
    // K6: out = ao @ Wout + b_out
    {
        GemmParams p = {};
        p.A = ao; p.B = Wout; p.C = out; p.bias = b_out;
        p.M = BATCH * NQ; p.N = DMODEL; p.K = INNER;
        p.lda = INNER; p.ldb = DMODEL; p.ldc = DMODEL;
        p.Z2 = 1; p.alpha = 1.0f;
        mma_gemm<128,128,16,64,64,false,false>
            <<<dim3(DMODEL/128, BATCH*NQ/128, 1), 128, SMEM_BIG>>>(p);
    }
}

// round 5
// speedup vs baseline: 1.0019x; 1.0019x over previous
#include <cuda_runtime.h>

// Problem constants
#define BATCH   4
#define NQ      1024
#define NJ      2048
#define DMODEL  768
#define HEADS   12
#define DHEAD   64
#define INNER   768
#define SCALE   0.125f

// ---------------------------------------------------------------------------
// Scratch
// ---------------------------------------------------------------------------
__device__ float g_q  [BATCH * NQ * INNER];
__device__ float g_kv [BATCH * NJ * 2 * INNER];
__device__ float g_dots[(size_t)BATCH * NQ * HEADS * NJ];
__device__ float g_ao [BATCH * NQ * INNER];

struct GemmParams {
    const float* A;
    const float* A2;
    const float* B;
    float*       C;
    const float* bias;
    int M, N, K;
    int lda, ldb, ldc;
    int Z2;
    long as1, as2, bs1, bs2, cs1, cs2;
    float alpha;
    int gatherSplit;
};

__device__ __forceinline__ float f2tf(float x) {
    unsigned u;
    asm("cvt.rna.tf32.f32 %0, %1;" : "=r"(u) : "f"(x));
    return __uint_as_float(u);
}

__device__ __forceinline__ void mma_tf32(float* c, const float* a, float b0, float b1) {
    asm volatile(
        "mma.sync.aligned.m16n8k8.row.col.f32.tf32.tf32.f32 "
        "{%0,%1,%2,%3},{%4,%5,%6,%7},{%8,%9},{%0,%1,%2,%3};"
        : "+f"(c[0]), "+f"(c[1]), "+f"(c[2]), "+f"(c[3])
        : "r"(__float_as_uint(a[0])), "r"(__float_as_uint(a[1])),
          "r"(__float_as_uint(a[2])), "r"(__float_as_uint(a[3])),
          "r"(__float_as_uint(b0)),  "r"(__float_as_uint(b1)));
}

// k-dependent XOR swizzle on the m/n index (keeps STS and LDS conflicts <=2-way)
__device__ __forceinline__ int sw(int k, int m) { return m ^ ((k & 12) >> 1); }

// ---------------------------------------------------------------------------
// Double-buffered 3xTF32 tensor-core GEMM (fp32-accurate).
// smem holds {hi,lo} interleaved float2; producer prefetches slab s+1 into
// registers while MMAs consume slab s.  One __syncthreads per slab.
//   A: [M,K] row-major (optional 2-source row gather)
//   B: BT=false -> [K,N] row-major;  BT=true -> [N,K] row-major
// ---------------------------------------------------------------------------
template<int BM, int BN, int BK, int WM, int WN, bool BT, bool GATHER>
__global__ void __launch_bounds__((BM/WM)*(BN/WN)*32, 2) mma_gemm(GemmParams p) {
    constexpr int WARPS_M = BM / WM;
    constexpr int WARPS_N = BN / WN;
    constexpr int THREADS = WARPS_M * WARPS_N * 32;
    constexpr int MT  = WM / 16;
    constexpr int NTL = WN / 8;
    constexpr int KS  = BK / 8;
    constexpr int LDA2 = BM + 4;   // float2 stride per k-row
    constexpr int LDB2 = BN + 4;
    constexpr int A_F4 = BM * BK / 4 / THREADS;
    constexpr int B_F4 = BN * BK / 4 / THREADS;

    extern __shared__ float2 smem[];
    float2* Abuf[2] = { smem, smem + BK * LDA2 };
    float2* Bbuf[2] = { smem + 2 * BK * LDA2, smem + 2 * BK * LDA2 + BK * LDB2 };

    const int z  = blockIdx.z;
    const int z1 = z / p.Z2;
    const int z2 = z - z1 * p.Z2;
    const float* A  = p.A + z1 * p.as1 + z2 * p.as2;
    const float* A2 = GATHER ? (p.A2 + z1 * p.as1) : nullptr;
    const float* B  = p.B + z1 * p.bs1 + z2 * p.bs2;
    float*       C  = p.C + z1 * p.cs1 + z2 * p.cs2;

    const int m0 = blockIdx.y * BM;
    const int n0 = blockIdx.x * BN;
    const int tid  = threadIdx.x;
    const int wid  = tid >> 5;
    const int lane = tid & 31;
    const int wm = wid % WARPS_M;
    const int wn = wid / WARPS_M;
    const int g = lane >> 2;
    const int t = lane & 3;

    float acc[MT][NTL][4];
#pragma unroll
    for (int mi = 0; mi < MT; mi++)
#pragma unroll
        for (int ni = 0; ni < NTL; ni++)
#pragma unroll
            for (int e = 0; e < 4; e++) acc[mi][ni][e] = 0.0f;

    float4 ra[A_F4], rb[B_F4];

    // ---- stage loaders (global -> regs) ----
    auto loadA = [&](int k0) {
#pragma unroll
        for (int i = 0; i < A_F4; i++) {
            int it  = tid + i * THREADS;
            int row = it / (BK / 4);
            int c4  = (it % (BK / 4)) * 4;
            const float* ap;
            if (GATHER) {
                int m = m0 + row;
                ap = (m < p.gatherSplit)
                         ? (A  + (long)m * p.lda)
                         : (A2 + (long)(m - p.gatherSplit) * p.lda);
            } else {
                ap = A + (long)(m0 + row) * p.lda;
            }
            ra[i] = *(const float4*)(ap + k0 + c4);
        }
    };
    auto loadB = [&](int k0) {
#pragma unroll
        for (int i = 0; i < B_F4; i++) {
            int it = tid + i * THREADS;
            if (BT) {
                int row = it / (BK / 4);
                int c4  = (it % (BK / 4)) * 4;
                rb[i] = *(const float4*)(B + (long)(n0 + row) * p.ldb + k0 + c4);
            } else {
                int row = it / (BN / 4);
                int c4  = (it % (BN / 4)) * 4;
                rb[i] = *(const float4*)(B + (long)(k0 + row) * p.ldb + n0 + c4);
            }
        }
    };
    // ---- stage storers (regs -> smem, tf32 hi/lo split) ----
    auto storeA = [&](int buf) {
        float2* As = Abuf[buf];
#pragma unroll
        for (int i = 0; i < A_F4; i++) {
            int it  = tid + i * THREADS;
            int row = it / (BK / 4);
            int c4  = (it % (BK / 4)) * 4;
            float vv[4] = {ra[i].x, ra[i].y, ra[i].z, ra[i].w};
#pragma unroll
            for (int e = 0; e < 4; e++) {
                int k = c4 + e;
                float hi = f2tf(vv[e]);
                As[k * LDA2 + sw(k, row)] = make_float2(hi, f2tf(vv[e] - hi));
            }
        }
    };
    auto storeB = [&](int buf) {
        float2* Bs = Bbuf[buf];
#pragma unroll
        for (int i = 0; i < B_F4; i++) {
            int it = tid + i * THREADS;
            float vv[4] = {rb[i].x, rb[i].y, rb[i].z, rb[i].w};
            if (BT) {
                int row = it / (BK / 4);
                int c4  = (it % (BK / 4)) * 4;
#pragma unroll
                for (int e = 0; e < 4; e++) {
                    int k = c4 + e;
                    float hi = f2tf(vv[e]);
                    Bs[k * LDB2 + sw(k, row)] = make_float2(hi, f2tf(vv[e] - hi));
                }
            } else {
                int row = it / (BN / 4);
                int c4  = (it % (BN / 4)) * 4;
#pragma unroll
                for (int e = 0; e < 4; e++) {
                    int n = c4 + e;
                    float hi = f2tf(vv[e]);
                    Bs[row * LDB2 + sw(row, n)] = make_float2(hi, f2tf(vv[e] - hi));
                }
            }
        }
    };

    const int S = p.K / BK;
    loadA(0); loadB(0);
    storeA(0); storeB(0);
    __syncthreads();

    for (int s = 0; s < S; s++) {
        if (s + 1 < S) { loadA((s + 1) * BK); loadB((s + 1) * BK); }

        const float2* As = Abuf[s & 1];
        const float2* Bs = Bbuf[s & 1];
#pragma unroll
        for (int ks = 0; ks < KS; ks++) {
            const int kb  = ks * 8;
            const int kr0 = kb + t;
            const int kr1 = kb + t + 4;
            const int s0  = (kr0 & 12) >> 1;
            const int s1  = (kr1 & 12) >> 1;

            float2 af[MT][4];
#pragma unroll
            for (int mi = 0; mi < MT; mi++) {
                int rb0 = wm * WM + mi * 16;
                af[mi][0] = As[kr0 * LDA2 + ((rb0 + g)     ^ s0)];
                af[mi][1] = As[kr0 * LDA2 + ((rb0 + g + 8) ^ s0)];
                af[mi][2] = As[kr1 * LDA2 + ((rb0 + g)     ^ s1)];
                af[mi][3] = As[kr1 * LDA2 + ((rb0 + g + 8) ^ s1)];
            }
#pragma unroll
            for (int ni = 0; ni < NTL; ni++) {
                int cb = wn * WN + ni * 8 + g;
                float2 b0 = Bs[kr0 * LDB2 + (cb ^ s0)];
                float2 b1 = Bs[kr1 * LDB2 + (cb ^ s1)];
#pragma unroll
                for (int mi = 0; mi < MT; mi++) {
                    float ah[4] = {af[mi][0].x, af[mi][1].x, af[mi][2].x, af[mi][3].x};
                    float al[4] = {af[mi][0].y, af[mi][1].y, af[mi][2].y, af[mi][3].y};
                    mma_tf32(acc[mi][ni], ah, b0.x, b1.x);  // hi*hi
                    mma_tf32(acc[mi][ni], ah, b0.y, b1.y);  // hi*lo
                    mma_tf32(acc[mi][ni], al, b0.x, b1.x);  // lo*hi
                }
            }
        }

        if (s + 1 < S) { storeA((s + 1) & 1); storeB((s + 1) & 1); }
        __syncthreads();
    }

    // ---- epilogue ----
#pragma unroll
    for (int mi = 0; mi < MT; mi++) {
        int r0 = m0 + wm * WM + mi * 16 + g;
#pragma unroll
        for (int ni = 0; ni < NTL; ni++) {
            int col = n0 + wn * WN + ni * 8 + t * 2;
            float bx = 0.f, by = 0.f;
            if (p.bias) { bx = p.bias[col]; by = p.bias[col + 1]; }
            float2 v0, v1;
            v0.x = acc[mi][ni][0] * p.alpha + bx;
            v0.y = acc[mi][ni][1] * p.alpha + by;
            v1.x = acc[mi][ni][2] * p.alpha + bx;
            v1.y = acc[mi][ni][3] * p.alpha + by;
            *(float2*)&C[(long)r0 * p.ldc + col]       = v0;
            *(float2*)&C[(long)(r0 + 8) * p.ldc + col] = v1;
        }
    }
}

// ---------------------------------------------------------------------------
// Register-resident talking-heads: pre-mix -> softmax -> post-mix, in-place.
// ---------------------------------------------------------------------------
__global__ void __launch_bounds__(512) mix_softmax2(
    float* __restrict__ dots,
    const float* __restrict__ pre_g,
    const float* __restrict__ post_g)
{
    __shared__ float s_pre[HEADS * HEADS], s_post[HEADS * HEADS];
    __shared__ float red[16][HEADS];
    __shared__ float bm[HEADS], bs[HEADS];

    const int tid = threadIdx.x;
    if (tid < HEADS * HEADS) { s_pre[tid] = pre_g[tid]; s_post[tid] = post_g[tid]; }
    __syncthreads();

    const long base = (long)blockIdx.x * (HEADS * NJ);
    const int j0 = tid * 4;
    const int w = tid >> 5, lane = tid & 31;

    float4 mx[HEADS];
#pragma unroll
    for (int gg = 0; gg < HEADS; gg++) mx[gg] = make_float4(0.f, 0.f, 0.f, 0.f);
#pragma unroll
    for (int h = 0; h < HEADS; h++) {
        float4 r = *(const float4*)(dots + base + (long)h * NJ + j0);
#pragma unroll
        for (int gg = 0; gg < HEADS; gg++) {
            float wv = s_pre[h * HEADS + gg];
            mx[gg].x += r.x * wv;
            mx[gg].y += r.y * wv;
            mx[gg].z += r.z * wv;
            mx[gg].w += r.w * wv;
        }
    }

    float m[HEADS];
#pragma unroll
    for (int gg = 0; gg < HEADS; gg++)
        m[gg] = fmaxf(fmaxf(mx[gg].x, mx[gg].y), fmaxf(mx[gg].z, mx[gg].w));
#pragma unroll
    for (int gg = 0; gg < HEADS; gg++)
#pragma unroll
        for (int o = 16; o; o >>= 1)
            m[gg] = fmaxf(m[gg], __shfl_xor_sync(0xFFFFFFFFu, m[gg], o));
#pragma unroll
    for (int gg = 0; gg < HEADS; gg++)
        if (lane == gg) red[w][gg] = m[gg];
    __syncthreads();
    if (tid < HEADS) {
        float mm = -1e30f;
#pragma unroll
        for (int ww = 0; ww < 16; ww++) mm = fmaxf(mm, red[ww][tid]);
        bm[tid] = mm;
    }
    __syncthreads();

    float s[HEADS];
#pragma unroll
    for (int gg = 0; gg < HEADS; gg++) {
        float mm = bm[gg];
        mx[gg].x = __expf(mx[gg].x - mm);
        mx[gg].y = __expf(mx[gg].y - mm);
        mx[gg].z = __expf(mx[gg].z - mm);
        mx[gg].w = __expf(mx[gg].w - mm);
        s[gg] = (mx[gg].x + mx[gg].y) + (mx[gg].z + mx[gg].w);
    }
#pragma unroll
    for (int gg = 0; gg < HEADS; gg++)
#pragma unroll
        for (int o = 16; o; o >>= 1)
            s[gg] += __shfl_xor_sync(0xFFFFFFFFu, s[gg], o);
    __syncthreads();
#pragma unroll
    for (int gg = 0; gg < HEADS; gg++)
        if (lane == gg) red[w][gg] = s[gg];
    __syncthreads();
    if (tid < HEADS) {
        float ss = 0.f;
#pragma unroll
        for (int ww = 0; ww < 16; ww++) ss += red[ww][tid];
        bs[tid] = ss;
    }
    __syncthreads();

#pragma unroll
    for (int gg = 0; gg < HEADS; gg++) {
        float inv = 1.0f / bs[gg];
        mx[gg].x *= inv; mx[gg].y *= inv; mx[gg].z *= inv; mx[gg].w *= inv;
    }

#pragma unroll
    for (int gg = 0; gg < HEADS; gg++) {
        float4 o = make_float4(0.f, 0.f, 0.f, 0.f);
#pragma unroll
        for (int h = 0; h < HEADS; h++) {
            float wv = s_post[h * HEADS + gg];
            o.x += mx[h].x * wv;
            o.y += mx[h].y * wv;
            o.z += mx[h].z * wv;
            o.w += mx[h].w * wv;
        }
        *(float4*)(dots + base + (long)gg * NJ + j0) = o;
    }
}

// ---------------------------------------------------------------------------
// Launch
// ---------------------------------------------------------------------------
#define SMEM_BIG  ((2*16*(128+4) + 2*16*(128+4)) * 8)   // 67584 B (128x128 cfg)
#define SMEM_K5   ((2*16*(128+4) + 2*16*(64+4)) * 8)    // 51200 B (128x64 cfg)

extern "C" void kernel_launch(void* const* d_in, const int* in_sizes, int n_in,
                              void* d_out, int out_size) {
    (void)in_sizes; (void)n_in; (void)out_size;
    const float* x        = (const float*)d_in[0];
    const float* context  = (const float*)d_in[1];
    const float* Wq       = (const float*)d_in[2];
    const float* Wkv      = (const float*)d_in[3];
    const float* mix_pre  = (const float*)d_in[4];
    const float* mix_post = (const float*)d_in[5];
    const float* Wout     = (const float*)d_in[6];
    const float* b_out    = (const float*)d_in[7];
    float* out = (float*)d_out;

    float *q, *kv, *dots, *ao;
    cudaGetSymbolAddress((void**)&q,    g_q);
    cudaGetSymbolAddress((void**)&kv,   g_kv);
    cudaGetSymbolAddress((void**)&dots, g_dots);
    cudaGetSymbolAddress((void**)&ao,   g_ao);

    const long Q_B  = (long)NQ * INNER;
    const long KV_B = (long)NJ * 2 * INNER;
    const long D_B  = (long)NQ * HEADS * NJ;

    static bool attr_done = false;
    if (!attr_done) {
        cudaFuncSetAttribute(mma_gemm<128,128,16,64,64,false,false>,
                             cudaFuncAttributeMaxDynamicSharedMemorySize, SMEM_BIG);
        cudaFuncSetAttribute(mma_gemm<128,128,16,64,64,false,true>,
                             cudaFuncAttributeMaxDynamicSharedMemorySize, SMEM_BIG);
        cudaFuncSetAttribute(mma_gemm<128,128,16,64,64,true,false>,
                             cudaFuncAttributeMaxDynamicSharedMemorySize, SMEM_BIG);
        cudaFuncSetAttribute(mma_gemm<128,64,16,64,32,false,false>,
                             cudaFuncAttributeMaxDynamicSharedMemorySize, SMEM_K5);
        attr_done = true;
    }

    // K1: q = x @ Wq
    {
        GemmParams p = {};
        p.A = x; p.B = Wq; p.C = q;
        p.M = BATCH * NQ; p.N = INNER; p.K = DMODEL;
        p.lda = DMODEL; p.ldb = INNER; p.ldc = INNER;
        p.Z2 = 1; p.alpha = 1.0f;
        mma_gemm<128,128,16,64,64,false,false>
            <<<dim3(INNER/128, BATCH*NQ/128, 1), 128, SMEM_BIG>>>(p);
    }
    // K2: kv = concat(x, context) @ Wkv
    {
        GemmParams p = {};
        p.A = x; p.A2 = context; p.B = Wkv; p.C = kv;
        p.M = NJ; p.N = 2 * INNER; p.K = DMODEL;
        p.lda = DMODEL; p.ldb = 2 * INNER; p.ldc = 2 * INNER;
        p.Z2 = 1; p.as1 = (long)NQ * DMODEL; p.cs1 = KV_B;
        p.alpha = 1.0f; p.gatherSplit = NQ;
        mma_gemm<128,128,16,64,64,false,true>
            <<<dim3(2*INNER/128, NJ/128, BATCH), 128, SMEM_BIG>>>(p);
    }
    // K3: dots = SCALE * q @ k^T   (NT, 48 batch-heads)
    {
        GemmParams p = {};
        p.A = q; p.B = kv; p.C = dots;
        p.M = NQ; p.N = NJ; p.K = DHEAD;
        p.lda = INNER; p.ldb = 2 * INNER; p.ldc = HEADS * NJ;
        p.Z2 = HEADS;
        p.as1 = Q_B;  p.as2 = DHEAD;
        p.bs1 = KV_B; p.bs2 = DHEAD;
        p.cs1 = D_B;  p.cs2 = NJ;
        p.alpha = SCALE;
        mma_gemm<128,128,16,64,64,true,false>
            <<<dim3(NJ/128, NQ/128, BATCH*HEADS), 128, SMEM_BIG>>>(p);
    }
    // K4: fused talking-heads softmax
    mix_softmax2<<<BATCH * NQ, 512>>>(dots, mix_pre, mix_post);
    // K5: ao = attn @ v   (NN, 48 batch-heads)
    {
        GemmParams p = {};
        p.A = dots; p.B = kv + INNER; p.C = ao;
        p.M = NQ; p.N = DHEAD; p.K = NJ;
        p.lda = HEADS * NJ; p.ldb = 2 * INNER; p.ldc = INNER;
        p.Z2 = HEADS;
        p.as1 = D_B;  p.as2 = NJ;
        p.bs1 = KV_B; p.bs2 = DHEAD;
        p.cs1 = Q_B;  p.cs2 = DHEAD;
        p.alpha = 1.0f;
        mma_gemm<128,64,16,64,32,false,false>
            <<<dim3(1, NQ/128, BATCH*HEADS), 128, SMEM_K5>>>(p);
    }
    // K6: out = ao @ Wout + b_out
    {
        GemmParams p = {};
        p.A = ao; p.B = Wout; p.C = out; p.bias = b_out;
        p.M = BATCH * NQ; p.N = DMODEL; p.K = INNER;
        p.lda = INNER; p.ldb = DMODEL; p.ldc = DMODEL;
        p.Z2 = 1; p.alpha = 1.0f;
        mma_gemm<128,128,16,64,64,false,false>
            <<<dim3(DMODEL/128, BATCH*NQ/128, 1), 128, SMEM_BIG>>>(p);
    }
}

// round 6
// speedup vs baseline: 1.7190x; 1.7158x over previous
#include <cuda_runtime.h>

// Problem constants
#define BATCH   4
#define NQ      1024
#define NJ      2048
#define DMODEL  768
#define HEADS   12
#define DHEAD   64
#define INNER   768
#define SCALE   0.125f

// ---------------------------------------------------------------------------
// Scratch
// ---------------------------------------------------------------------------
__device__ float g_q  [BATCH * NQ * INNER];
__device__ float g_kv [BATCH * NJ * 2 * INNER];
__device__ float g_dots[(size_t)BATCH * NQ * HEADS * NJ];
__device__ float g_ao [BATCH * NQ * INNER];

struct GemmParams {
    const float* A;
    const float* A2;
    const float* B;
    float*       C;
    const float* bias;
    int M, N, K;
    int lda, ldb, ldc;
    int Z2;
    long as1, as2, bs1, bs2, cs1, cs2;
    float alpha;
    int gatherSplit;
};

__device__ __forceinline__ float f2tf(float x) {
    unsigned u;
    asm("cvt.rna.tf32.f32 %0, %1;" : "=r"(u) : "f"(x));
    return __uint_as_float(u);
}

__device__ __forceinline__ void mma_tf32(float* c, const float* a, float b0, float b1) {
    asm volatile(
        "mma.sync.aligned.m16n8k8.row.col.f32.tf32.tf32.f32 "
        "{%0,%1,%2,%3},{%4,%5,%6,%7},{%8,%9},{%0,%1,%2,%3};"
        : "+f"(c[0]), "+f"(c[1]), "+f"(c[2]), "+f"(c[3])
        : "r"(__float_as_uint(a[0])), "r"(__float_as_uint(a[1])),
          "r"(__float_as_uint(a[2])), "r"(__float_as_uint(a[3])),
          "r"(__float_as_uint(b0)),  "r"(__float_as_uint(b1)));
}

__device__ __forceinline__ void cp16(void* smem_dst, const void* gsrc) {
    unsigned d = (unsigned)__cvta_generic_to_shared(smem_dst);
    asm volatile("cp.async.cg.shared.global [%0], [%1], 16;" :: "r"(d), "l"(gsrc));
}
__device__ __forceinline__ void cp_commit() {
    asm volatile("cp.async.commit_group;");
}
template<int N>
__device__ __forceinline__ void cp_wait() {
    asm volatile("cp.async.wait_group %0;" :: "n"(N));
}

// ---------------------------------------------------------------------------
// cp.async 3-stage pipelined 3xTF32 tensor-core GEMM (fp32-accurate).
// smem holds RAW fp32 (cp.async is a pure copy); the tf32 hi/lo split happens
// at fragment-load time (hi = cvt.rna, lo = x - hi, lo fed raw — HW truncates).
//   A: [M,K] row-major (optional 2-source row gather), smem [BM][BK+4]
//   B: BT=false -> [K,N] row-major, smem [BK][BN+4]
//      BT=true  -> [N,K] row-major, smem [BN][BK+4]
// ---------------------------------------------------------------------------
template<int BM, int BN, int BK, int WM, int WN, int STAGES, bool BT, bool GATHER>
__global__ void __launch_bounds__(256, 2) mma_gemm(GemmParams p) {
    constexpr int WARPS_M = BM / WM;
    constexpr int WARPS_N = BN / WN;
    static_assert(WARPS_M * WARPS_N == 8, "256 threads");
    constexpr int MT  = WM / 16;
    constexpr int NTL = WN / 8;
    constexpr int KS  = BK / 8;
    constexpr int A_LD = BK + 4;                       // 20 floats/row
    constexpr int B_LD = BT ? (BK + 4) : (BN + 4);
    constexpr int A_SZ = BM * A_LD;
    constexpr int B_SZ = BT ? (BN * (BK + 4)) : (BK * (BN + 4));
    constexpr int A_CH = BM * BK / 4 / 256;            // 16B chunks per thread
    constexpr int B_CH = BN * BK / 4 / 256;

    extern __shared__ float smem[];
    float* Ab = smem;                   // [STAGES][A_SZ]
    float* Bb = smem + STAGES * A_SZ;   // [STAGES][B_SZ]

    const int z  = blockIdx.z;
    const int z1 = z / p.Z2;
    const int z2 = z - z1 * p.Z2;
    const float* A  = p.A + z1 * p.as1 + z2 * p.as2;
    const float* A2 = GATHER ? (p.A2 + z1 * p.as1) : nullptr;
    const float* B  = p.B + z1 * p.bs1 + z2 * p.bs2;
    float*       C  = p.C + z1 * p.cs1 + z2 * p.cs2;

    const int m0 = blockIdx.y * BM;
    const int n0 = blockIdx.x * BN;
    const int tid  = threadIdx.x;
    const int wid  = tid >> 5;
    const int lane = tid & 31;
    const int wm = wid % WARPS_M;
    const int wn = wid / WARPS_M;
    const int g = lane >> 2;
    const int t = lane & 3;

    float acc[MT][NTL][4];
#pragma unroll
    for (int mi = 0; mi < MT; mi++)
#pragma unroll
        for (int ni = 0; ni < NTL; ni++)
#pragma unroll
            for (int e = 0; e < 4; e++) acc[mi][ni][e] = 0.0f;

    auto issue = [&](int k0, int st) {
        float* As = Ab + st * A_SZ;
        float* Bs = Bb + st * B_SZ;
#pragma unroll
        for (int i = 0; i < A_CH; i++) {
            int it  = tid + i * 256;
            int row = it / (BK / 4);
            int c4  = (it % (BK / 4)) * 4;
            const float* src;
            if (GATHER) {
                int m = m0 + row;
                src = (m < p.gatherSplit)
                          ? (A  + (long)m * p.lda + k0 + c4)
                          : (A2 + (long)(m - p.gatherSplit) * p.lda + k0 + c4);
            } else {
                src = A + (long)(m0 + row) * p.lda + k0 + c4;
            }
            cp16(&As[row * A_LD + c4], src);
        }
#pragma unroll
        for (int i = 0; i < B_CH; i++) {
            int it = tid + i * 256;
            if (BT) {
                int row = it / (BK / 4);         // n
                int c4  = (it % (BK / 4)) * 4;   // k
                cp16(&Bs[row * B_LD + c4],
                     B + (long)(n0 + row) * p.ldb + k0 + c4);
            } else {
                int row = it / (BN / 4);         // k
                int c4  = (it % (BN / 4)) * 4;   // n
                cp16(&Bs[row * B_LD + c4],
                     B + (long)(k0 + row) * p.ldb + n0 + c4);
            }
        }
    };

    const int S = p.K / BK;
    int fetch = 0;
    for (; fetch < STAGES - 1 && fetch < S; fetch++) {
        issue(fetch * BK, fetch);
        cp_commit();
    }

    for (int s = 0; s < S; s++) {
        cp_wait<STAGES - 2>();
        __syncthreads();

        const float* As = Ab + (s % STAGES) * A_SZ;
        const float* Bs = Bb + (s % STAGES) * B_SZ;
#pragma unroll
        for (int ks = 0; ks < KS; ks++) {
            const int kb = ks * 8;
            float ah[MT][4], al[MT][4];
#pragma unroll
            for (int mi = 0; mi < MT; mi++) {
                int rb0 = wm * WM + mi * 16;
                float x0 = As[(rb0 + g)     * A_LD + kb + t];
                float x1 = As[(rb0 + g + 8) * A_LD + kb + t];
                float x2 = As[(rb0 + g)     * A_LD + kb + t + 4];
                float x3 = As[(rb0 + g + 8) * A_LD + kb + t + 4];
                ah[mi][0] = f2tf(x0); al[mi][0] = x0 - ah[mi][0];
                ah[mi][1] = f2tf(x1); al[mi][1] = x1 - ah[mi][1];
                ah[mi][2] = f2tf(x2); al[mi][2] = x2 - ah[mi][2];
                ah[mi][3] = f2tf(x3); al[mi][3] = x3 - ah[mi][3];
            }
#pragma unroll
            for (int ni = 0; ni < NTL; ni++) {
                int cb = wn * WN + ni * 8 + g;
                float x0 = BT ? Bs[cb * B_LD + kb + t]
                              : Bs[(kb + t) * B_LD + cb];
                float x1 = BT ? Bs[cb * B_LD + kb + t + 4]
                              : Bs[(kb + t + 4) * B_LD + cb];
                float bh0 = f2tf(x0), bl0 = x0 - bh0;
                float bh1 = f2tf(x1), bl1 = x1 - bh1;
#pragma unroll
                for (int mi = 0; mi < MT; mi++) {
                    mma_tf32(acc[mi][ni], ah[mi], bh0, bh1);  // hi*hi
                    mma_tf32(acc[mi][ni], ah[mi], bl0, bl1);  // hi*lo
                    mma_tf32(acc[mi][ni], al[mi], bh0, bh1);  // lo*hi
                }
            }
        }

        if (fetch < S) {
            issue(fetch * BK, fetch % STAGES);
            fetch++;
        }
        cp_commit();   // empty groups near the tail keep the count consistent
    }

    // ---- epilogue ----
#pragma unroll
    for (int mi = 0; mi < MT; mi++) {
        int r0 = m0 + wm * WM + mi * 16 + g;
#pragma unroll
        for (int ni = 0; ni < NTL; ni++) {
            int col = n0 + wn * WN + ni * 8 + t * 2;
            float bx = 0.f, by = 0.f;
            if (p.bias) { bx = p.bias[col]; by = p.bias[col + 1]; }
            float2 v0, v1;
            v0.x = acc[mi][ni][0] * p.alpha + bx;
            v0.y = acc[mi][ni][1] * p.alpha + by;
            v1.x = acc[mi][ni][2] * p.alpha + bx;
            v1.y = acc[mi][ni][3] * p.alpha + by;
            *(float2*)&C[(long)r0 * p.ldc + col]       = v0;
            *(float2*)&C[(long)(r0 + 8) * p.ldc + col] = v1;
        }
    }
}

// ---------------------------------------------------------------------------
// Register-resident talking-heads: pre-mix -> softmax -> post-mix, in-place.
// (unchanged — known 283 us, memory-bound at its occupancy)
// ---------------------------------------------------------------------------
__global__ void __launch_bounds__(512) mix_softmax2(
    float* __restrict__ dots,
    const float* __restrict__ pre_g,
    const float* __restrict__ post_g)
{
    __shared__ float s_pre[HEADS * HEADS], s_post[HEADS * HEADS];
    __shared__ float red[16][HEADS];
    __shared__ float bm[HEADS], bs[HEADS];

    const int tid = threadIdx.x;
    if (tid < HEADS * HEADS) { s_pre[tid] = pre_g[tid]; s_post[tid] = post_g[tid]; }
    __syncthreads();

    const long base = (long)blockIdx.x * (HEADS * NJ);
    const int j0 = tid * 4;
    const int w = tid >> 5, lane = tid & 31;

    float4 mx[HEADS];
#pragma unroll
    for (int gg = 0; gg < HEADS; gg++) mx[gg] = make_float4(0.f, 0.f, 0.f, 0.f);
#pragma unroll
    for (int h = 0; h < HEADS; h++) {
        float4 r = *(const float4*)(dots + base + (long)h * NJ + j0);
#pragma unroll
        for (int gg = 0; gg < HEADS; gg++) {
            float wv = s_pre[h * HEADS + gg];
            mx[gg].x += r.x * wv;
            mx[gg].y += r.y * wv;
            mx[gg].z += r.z * wv;
            mx[gg].w += r.w * wv;
        }
    }

    float m[HEADS];
#pragma unroll
    for (int gg = 0; gg < HEADS; gg++)
        m[gg] = fmaxf(fmaxf(mx[gg].x, mx[gg].y), fmaxf(mx[gg].z, mx[gg].w));
#pragma unroll
    for (int gg = 0; gg < HEADS; gg++)
#pragma unroll
        for (int o = 16; o; o >>= 1)
            m[gg] = fmaxf(m[gg], __shfl_xor_sync(0xFFFFFFFFu, m[gg], o));
#pragma unroll
    for (int gg = 0; gg < HEADS; gg++)
        if (lane == gg) red[w][gg] = m[gg];
    __syncthreads();
    if (tid < HEADS) {
        float mm = -1e30f;
#pragma unroll
        for (int ww = 0; ww < 16; ww++) mm = fmaxf(mm, red[ww][tid]);
        bm[tid] = mm;
    }
    __syncthreads();

    float s[HEADS];
#pragma unroll
    for (int gg = 0; gg < HEADS; gg++) {
        float mm = bm[gg];
        mx[gg].x = __expf(mx[gg].x - mm);
        mx[gg].y = __expf(mx[gg].y - mm);
        mx[gg].z = __expf(mx[gg].z - mm);
        mx[gg].w = __expf(mx[gg].w - mm);
        s[gg] = (mx[gg].x + mx[gg].y) + (mx[gg].z + mx[gg].w);
    }
#pragma unroll
    for (int gg = 0; gg < HEADS; gg++)
#pragma unroll
        for (int o = 16; o; o >>= 1)
            s[gg] += __shfl_xor_sync(0xFFFFFFFFu, s[gg], o);
    __syncthreads();
#pragma unroll
    for (int gg = 0; gg < HEADS; gg++)
        if (lane == gg) red[w][gg] = s[gg];
    __syncthreads();
    if (tid < HEADS) {
        float ss = 0.f;
#pragma unroll
        for (int ww = 0; ww < 16; ww++) ss += red[ww][tid];
        bs[tid] = ss;
    }
    __syncthreads();

#pragma unroll
    for (int gg = 0; gg < HEADS; gg++) {
        float inv = 1.0f / bs[gg];
        mx[gg].x *= inv; mx[gg].y *= inv; mx[gg].z *= inv; mx[gg].w *= inv;
    }

#pragma unroll
    for (int gg = 0; gg < HEADS; gg++) {
        float4 o = make_float4(0.f, 0.f, 0.f, 0.f);
#pragma unroll
        for (int h = 0; h < HEADS; h++) {
            float wv = s_post[h * HEADS + gg];
            o.x += mx[h].x * wv;
            o.y += mx[h].y * wv;
            o.z += mx[h].z * wv;
            o.w += mx[h].w * wv;
        }
        *(float4*)(dots + base + (long)gg * NJ + j0) = o;
    }
}

// ---------------------------------------------------------------------------
// Launch
// ---------------------------------------------------------------------------
// smem bytes: STAGES * (A_SZ + B_SZ) * 4
#define SMEM_NN  (3 * (128*20 + 16*132) * 4)   // 56064  (BT=false, BN=128)
#define SMEM_BT  (3 * (128*20 + 128*20) * 4)   // 61440  (BT=true,  BN=128)
#define SMEM_K5  (3 * (128*20 + 16*68)  * 4)   // 43776  (BT=false, BN=64)

extern "C" void kernel_launch(void* const* d_in, const int* in_sizes, int n_in,
                              void* d_out, int out_size) {
    (void)in_sizes; (void)n_in; (void)out_size;
    const float* x        = (const float*)d_in[0];
    const float* context  = (const float*)d_in[1];
    const float* Wq       = (const float*)d_in[2];
    const float* Wkv      = (const float*)d_in[3];
    const float* mix_pre  = (const float*)d_in[4];
    const float* mix_post = (const float*)d_in[5];
    const float* Wout     = (const float*)d_in[6];
    const float* b_out    = (const float*)d_in[7];
    float* out = (float*)d_out;

    float *q, *kv, *dots, *ao;
    cudaGetSymbolAddress((void**)&q,    g_q);
    cudaGetSymbolAddress((void**)&kv,   g_kv);
    cudaGetSymbolAddress((void**)&dots, g_dots);
    cudaGetSymbolAddress((void**)&ao,   g_ao);

    const long Q_B  = (long)NQ * INNER;
    const long KV_B = (long)NJ * 2 * INNER;
    const long D_B  = (long)NQ * HEADS * NJ;

    cudaFuncSetAttribute(mma_gemm<128,128,16,32,64,3,false,false>,
                         cudaFuncAttributeMaxDynamicSharedMemorySize, SMEM_NN);
    cudaFuncSetAttribute(mma_gemm<128,128,16,32,64,3,false,true>,
                         cudaFuncAttributeMaxDynamicSharedMemorySize, SMEM_NN);
    cudaFuncSetAttribute(mma_gemm<128,128,16,32,64,3,true,false>,
                         cudaFuncAttributeMaxDynamicSharedMemorySize, SMEM_BT);
    cudaFuncSetAttribute(mma_gemm<128,64,16,32,32,3,false,false>,
                         cudaFuncAttributeMaxDynamicSharedMemorySize, SMEM_K5);

    // K1: q = x @ Wq
    {
        GemmParams p = {};
        p.A = x; p.B = Wq; p.C = q;
        p.M = BATCH * NQ; p.N = INNER; p.K = DMODEL;
        p.lda = DMODEL; p.ldb = INNER; p.ldc = INNER;
        p.Z2 = 1; p.alpha = 1.0f;
        mma_gemm<128,128,16,32,64,3,false,false>
            <<<dim3(INNER/128, BATCH*NQ/128, 1), 256, SMEM_NN>>>(p);
    }
    // K2: kv = concat(x, context) @ Wkv
    {
        GemmParams p = {};
        p.A = x; p.A2 = context; p.B = Wkv; p.C = kv;
        p.M = NJ; p.N = 2 * INNER; p.K = DMODEL;
        p.lda = DMODEL; p.ldb = 2 * INNER; p.ldc = 2 * INNER;
        p.Z2 = 1; p.as1 = (long)NQ * DMODEL; p.cs1 = KV_B;
        p.alpha = 1.0f; p.gatherSplit = NQ;
        mma_gemm<128,128,16,32,64,3,false,true>
            <<<dim3(2*INNER/128, NJ/128, BATCH), 256, SMEM_NN>>>(p);
    }
    // K3: dots = SCALE * q @ k^T   (NT, 48 batch-heads)
    {
        GemmParams p = {};
        p.A = q; p.B = kv; p.C = dots;
        p.M = NQ; p.N = NJ; p.K = DHEAD;
        p.lda = INNER; p.ldb = 2 * INNER; p.ldc = HEADS * NJ;
        p.Z2 = HEADS;
        p.as1 = Q_B;  p.as2 = DHEAD;
        p.bs1 = KV_B; p.bs2 = DHEAD;
        p.cs1 = D_B;  p.cs2 = NJ;
        p.alpha = SCALE;
        mma_gemm<128,128,16,32,64,3,true,false>
            <<<dim3(NJ/128, NQ/128, BATCH*HEADS), 256, SMEM_BT>>>(p);
    }
    // K4: fused talking-heads softmax
    mix_softmax2<<<BATCH * NQ, 512>>>(dots, mix_pre, mix_post);
    // K5: ao = attn @ v   (NN, 48 batch-heads)
    {
        GemmParams p = {};
        p.A = dots; p.B = kv + INNER; p.C = ao;
        p.M = NQ; p.N = DHEAD; p.K = NJ;
        p.lda = HEADS * NJ; p.ldb = 2 * INNER; p.ldc = INNER;
        p.Z2 = HEADS;
        p.as1 = D_B;  p.as2 = NJ;
        p.bs1 = KV_B; p.bs2 = DHEAD;
        p.cs1 = Q_B;  p.cs2 = DHEAD;
        p.alpha = 1.0f;
        mma_gemm<128,64,16,32,32,3,false,false>
            <<<dim3(1, NQ/128, BATCH*HEADS), 256, SMEM_K5>>>(p);
    }
    // K6: out = ao @ Wout + b_out
    {
        GemmParams p = {};
        p.A = ao; p.B = Wout; p.C = out; p.bias = b_out;
        p.M = BATCH * NQ; p.N = DMODEL; p.K = INNER;
        p.lda = INNER; p.ldb = DMODEL; p.ldc = DMODEL;
        p.Z2 = 1; p.alpha = 1.0f;
        mma_gemm<128,128,16,32,64,3,false,false>
            <<<dim3(DMODEL/128, BATCH*NQ/128, 1), 256, SMEM_NN>>>(p);
    }
}

// round 7
// speedup vs baseline: 2.4526x; 1.4268x over previous
#include <cuda_runtime.h>

// Problem constants
#define BATCH   4
#define NQ      1024
#define NJ      2048
#define DMODEL  768
#define HEADS   12
#define DHEAD   64
#define INNER   768
#define SCALE   0.125f

// ---------------------------------------------------------------------------
// Scratch: packed bf16x2 hi/lo operand arrays + fp32 intermediates
// word(r, k2) packs elements (2*k2, 2*k2+1) of the contraction dim:
// low 16 bits = even index, high 16 = odd index.
// ---------------------------------------------------------------------------
__device__ unsigned g_xch[(size_t)BATCH * NJ * (DMODEL/2)];   // concat(x,ctx), pack d
__device__ unsigned g_xcl[(size_t)BATCH * NJ * (DMODEL/2)];
__device__ unsigned g_wqh[(DMODEL/2) * INNER];                 // Wq, pack d (rows)
__device__ unsigned g_wql[(DMODEL/2) * INNER];
__device__ unsigned g_wkvh[(DMODEL/2) * 2 * INNER];
__device__ unsigned g_wkvl[(DMODEL/2) * 2 * INNER];
__device__ unsigned g_wouth[(INNER/2) * DMODEL];
__device__ unsigned g_woutl[(INNER/2) * DMODEL];
__device__ unsigned g_qh[BATCH * NQ * (INNER/2)];              // q, pack dh
__device__ unsigned g_ql[BATCH * NQ * (INNER/2)];
__device__ float    g_kv[(size_t)BATCH * NJ * 2 * INNER];      // fp32 kv (K2 out)
__device__ unsigned g_kh[(size_t)BATCH * NJ * (INNER/2)];      // k, pack dh
__device__ unsigned g_kl[(size_t)BATCH * NJ * (INNER/2)];
__device__ unsigned g_vh[(size_t)BATCH * (NJ/2) * INNER];      // v, pack j (rows)
__device__ unsigned g_vl[(size_t)BATCH * (NJ/2) * INNER];
__device__ float    g_dots[(size_t)BATCH * NQ * HEADS * NJ];   // fp32 logits
__device__ unsigned g_ath[(size_t)BATCH * NQ * HEADS * (NJ/2)]; // attn, pack j
__device__ unsigned g_atl[(size_t)BATCH * NQ * HEADS * (NJ/2)];
__device__ unsigned g_aoh[BATCH * NQ * (INNER/2)];             // attn-out, pack hd
__device__ unsigned g_aol[BATCH * NQ * (INNER/2)];

// ---------------------------------------------------------------------------
// Helpers
// ---------------------------------------------------------------------------
__device__ __forceinline__ unsigned pk(float e, float o) {   // low=e, high=o
    unsigned d;
    asm("cvt.rn.bf16x2.f32 %0, %1, %2;" : "=r"(d) : "f"(o), "f"(e));
    return d;
}
__device__ __forceinline__ float lo_f(unsigned w) { return __uint_as_float(w << 16); }
__device__ __forceinline__ float hi_f(unsigned w) { return __uint_as_float(w & 0xffff0000u); }

__device__ __forceinline__ void split2(float e, float o, unsigned& h, unsigned& l) {
    h = pk(e, o);
    l = pk(e - lo_f(h), o - hi_f(h));
}

__device__ __forceinline__ void mma_bf16(float* c, const unsigned* a, unsigned b0, unsigned b1) {
    asm volatile(
        "mma.sync.aligned.m16n8k16.row.col.f32.bf16.bf16.f32 "
        "{%0,%1,%2,%3},{%4,%5,%6,%7},{%8,%9},{%0,%1,%2,%3};"
        : "+f"(c[0]), "+f"(c[1]), "+f"(c[2]), "+f"(c[3])
        : "r"(a[0]), "r"(a[1]), "r"(a[2]), "r"(a[3]), "r"(b0), "r"(b1));
}

__device__ __forceinline__ void cp16(void* smem_dst, const void* gsrc) {
    unsigned d = (unsigned)__cvta_generic_to_shared(smem_dst);
    asm volatile("cp.async.cg.shared.global [%0], [%1], 16;" :: "r"(d), "l"(gsrc));
}
__device__ __forceinline__ void cp_commit() { asm volatile("cp.async.commit_group;"); }
template<int N>
__device__ __forceinline__ void cp_wait() { asm volatile("cp.async.wait_group %0;" :: "n"(N)); }

// ---------------------------------------------------------------------------
// Pack kernels (fp32 -> bf16 hi/lo words)
// ---------------------------------------------------------------------------
// pack along columns (contiguous): dst[r][c2] = {src[r][2c2], src[r][2c2+1]}
__global__ void pack_cols_g(const float* __restrict__ src, long srs,
                            unsigned* __restrict__ dh, unsigned* __restrict__ dl,
                            long drs, int g8pr, long total) {
    long id = (long)blockIdx.x * blockDim.x + threadIdx.x;
    if (id >= total) return;
    int c8 = (int)(id % g8pr);
    long r  = id / g8pr;
    const float* s = src + r * srs + (long)c8 * 8;
    float4 v0 = *(const float4*)s;
    float4 v1 = *(const float4*)(s + 4);
    unsigned h[4], l[4];
    split2(v0.x, v0.y, h[0], l[0]);
    split2(v0.z, v0.w, h[1], l[1]);
    split2(v1.x, v1.y, h[2], l[2]);
    split2(v1.z, v1.w, h[3], l[3]);
    long o = r * drs + (long)c8 * 4;
    *(uint4*)(dh + o) = make_uint4(h[0], h[1], h[2], h[3]);
    *(uint4*)(dl + o) = make_uint4(l[0], l[1], l[2], l[3]);
}

// pack along rows: dst[r2][c] = {src[2r2][c], src[2r2+1][c]}
__global__ void pack_rows_g(const float* __restrict__ src, long srs,
                            unsigned* __restrict__ dh, unsigned* __restrict__ dl,
                            long drs, int c4pr, long total) {
    long id = (long)blockIdx.x * blockDim.x + threadIdx.x;
    if (id >= total) return;
    int c4 = (int)(id % c4pr);
    long r2 = id / c4pr;
    const float* s0 = src + (2 * r2) * srs + (long)c4 * 4;
    const float* s1 = s0 + srs;
    float4 a = *(const float4*)s0;
    float4 b = *(const float4*)s1;
    unsigned h[4], l[4];
    split2(a.x, b.x, h[0], l[0]);
    split2(a.y, b.y, h[1], l[1]);
    split2(a.z, b.z, h[2], l[2]);
    split2(a.w, b.w, h[3], l[3]);
    long o = r2 * drs + (long)c4 * 4;
    *(uint4*)(dh + o) = make_uint4(h[0], h[1], h[2], h[3]);
    *(uint4*)(dl + o) = make_uint4(l[0], l[1], l[2], l[3]);
}

// pack concat(x, context) along d
__global__ void pack_xc(const float* __restrict__ x, const float* __restrict__ ctx,
                        unsigned* __restrict__ dh, unsigned* __restrict__ dl) {
    long id = (long)blockIdx.x * blockDim.x + threadIdx.x;   // 786432
    int c8 = (int)(id % 96);
    long rj = id / 96;
    int j = (int)(rj % NJ);
    int b = (int)(rj / NJ);
    const float* src = (j < NQ) ? x   + ((long)b * NQ + j)      * DMODEL
                                : ctx + ((long)b * NQ + j - NQ) * DMODEL;
    float4 v0 = *(const float4*)(src + c8 * 8);
    float4 v1 = *(const float4*)(src + c8 * 8 + 4);
    unsigned h[4], l[4];
    split2(v0.x, v0.y, h[0], l[0]);
    split2(v0.z, v0.w, h[1], l[1]);
    split2(v1.x, v1.y, h[2], l[2]);
    split2(v1.z, v1.w, h[3], l[3]);
    long o = rj * 384 + (long)c8 * 4;
    *(uint4*)(dh + o) = make_uint4(h[0], h[1], h[2], h[3]);
    *(uint4*)(dl + o) = make_uint4(l[0], l[1], l[2], l[3]);
}

// ---------------------------------------------------------------------------
// bf16x3 GEMM: pre-packed hi/lo operands, 2-stage cp.async pipeline, BK=32.
//   A: [M][K/2] words, pack-k.  B: BT ? [N][K/2] words : [K/2][N] words (pack-k rows)
//   C: fp32 (alpha, +bias)  or packed hi/lo words (PACKO)
// ---------------------------------------------------------------------------
struct GP {
    const unsigned *Ah, *Al, *Bh, *Bl;
    float* C;
    unsigned *Ch, *Cl;
    const float* bias;
    int K;
    int ldaw, ldbw, ldc;     // ldaw/ldbw words; ldc: elems (fp32) or words (PACKO)
    int Z2;
    long as1, as2, bs1, bs2, cs1, cs2;
    float alpha;
};

template<int BM, int BN, int WM, int WN, bool BT, bool PACKO>
__global__ void __launch_bounds__(256, 2) bf16_gemm(GP p) {
    constexpr int WARPS_M = BM / WM;
    constexpr int WARPS_N = BN / WN;
    static_assert(WARPS_M * WARPS_N == 8, "256 threads");
    constexpr int MT  = WM / 16;
    constexpr int NTL = WN / 8;
    constexpr int AW   = 20;                                // word stride, A rows
    constexpr int BW   = BT ? 20 : (BN + 4);
    constexpr int A_SZ = BM * AW;
    constexpr int B_SZ = BT ? (BN * 20) : (16 * (BN + 4));
    constexpr int ST   = 2 * (A_SZ + B_SZ);                 // hi+lo, one stage
    constexpr int A_CH = BM * 16 / 4 / 256;                 // chunks/thread/array
    constexpr int B_CH = BN * 16 / 4 / 256;

    extern __shared__ unsigned sm[];

    const int z  = blockIdx.z;
    const int z1 = z / p.Z2;
    const int z2 = z - z1 * p.Z2;
    const unsigned* gAh = p.Ah + z1 * p.as1 + z2 * p.as2;
    const unsigned* gAl = p.Al + z1 * p.as1 + z2 * p.as2;
    const unsigned* gBh = p.Bh + z1 * p.bs1 + z2 * p.bs2;
    const unsigned* gBl = p.Bl + z1 * p.bs1 + z2 * p.bs2;

    const int m0 = blockIdx.y * BM;
    const int n0 = blockIdx.x * BN;
    const int tid  = threadIdx.x;
    const int wid  = tid >> 5;
    const int lane = tid & 31;
    const int wm = wid % WARPS_M;
    const int wn = wid / WARPS_M;
    const int g = lane >> 2;
    const int t = lane & 3;

    float acc[MT][NTL][4];
#pragma unroll
    for (int mi = 0; mi < MT; mi++)
#pragma unroll
        for (int ni = 0; ni < NTL; ni++)
#pragma unroll
            for (int e = 0; e < 4; e++) acc[mi][ni][e] = 0.0f;

    auto issue = [&](int s) {
        const int st = s & 1;
        unsigned* Ah = sm + st * ST;
        unsigned* Al = Ah + A_SZ;
        unsigned* Bh = Al + A_SZ;
        unsigned* Bl = Bh + B_SZ;
        const int k0w = s * 16;
#pragma unroll
        for (int i = 0; i < A_CH; i++) {
            int c   = tid + i * 256;
            int row = c >> 2;
            int cw  = (c & 3) << 2;
            long go = (long)(m0 + row) * p.ldaw + k0w + cw;
            cp16(Ah + row * AW + cw, gAh + go);
            cp16(Al + row * AW + cw, gAl + go);
        }
#pragma unroll
        for (int i = 0; i < B_CH; i++) {
            int c = tid + i * 256;
            if (BT) {
                int row = c >> 2;
                int cw  = (c & 3) << 2;
                long go = (long)(n0 + row) * p.ldbw + k0w + cw;
                cp16(Bh + row * BW + cw, gBh + go);
                cp16(Bl + row * BW + cw, gBl + go);
            } else {
                int row = c / (BN / 4);
                int cw  = (c % (BN / 4)) << 2;
                long go = (long)(k0w + row) * p.ldbw + n0 + cw;
                cp16(Bh + row * BW + cw, gBh + go);
                cp16(Bl + row * BW + cw, gBl + go);
            }
        }
    };

    const int S = p.K / 32;
    issue(0);
    cp_commit();

    for (int s = 0; s < S; s++) {
        if (s + 1 < S) {
            issue(s + 1);
            cp_commit();
            cp_wait<1>();
        } else {
            cp_wait<0>();
        }
        __syncthreads();

        const int st = s & 1;
        const unsigned* Ah = sm + st * ST;
        const unsigned* Al = Ah + A_SZ;
        const unsigned* Bh = Al + A_SZ;
        const unsigned* Bl = Bh + B_SZ;

#pragma unroll
        for (int ks = 0; ks < 2; ks++) {
            const int k2b = ks * 8;
            unsigned ah[MT][4], al[MT][4];
#pragma unroll
            for (int mi = 0; mi < MT; mi++) {
                int r0 = wm * WM + mi * 16;
                ah[mi][0] = Ah[(r0 + g)     * AW + k2b + t];
                ah[mi][1] = Ah[(r0 + 8 + g) * AW + k2b + t];
                ah[mi][2] = Ah[(r0 + g)     * AW + k2b + t + 4];
                ah[mi][3] = Ah[(r0 + 8 + g) * AW + k2b + t + 4];
                al[mi][0] = Al[(r0 + g)     * AW + k2b + t];
                al[mi][1] = Al[(r0 + 8 + g) * AW + k2b + t];
                al[mi][2] = Al[(r0 + g)     * AW + k2b + t + 4];
                al[mi][3] = Al[(r0 + 8 + g) * AW + k2b + t + 4];
            }
#pragma unroll
            for (int ni = 0; ni < NTL; ni++) {
                int cb = wn * WN + ni * 8 + g;
                unsigned bh0, bh1, bl0, bl1;
                if (BT) {
                    bh0 = Bh[cb * BW + k2b + t];
                    bh1 = Bh[cb * BW + k2b + t + 4];
                    bl0 = Bl[cb * BW + k2b + t];
                    bl1 = Bl[cb * BW + k2b + t + 4];
                } else {
                    bh0 = Bh[(k2b + t)     * BW + cb];
                    bh1 = Bh[(k2b + t + 4) * BW + cb];
                    bl0 = Bl[(k2b + t)     * BW + cb];
                    bl1 = Bl[(k2b + t + 4) * BW + cb];
                }
#pragma unroll
                for (int mi = 0; mi < MT; mi++) {
                    mma_bf16(acc[mi][ni], ah[mi], bh0, bh1);   // hi*hi
                    mma_bf16(acc[mi][ni], ah[mi], bl0, bl1);   // hi*lo
                    mma_bf16(acc[mi][ni], al[mi], bh0, bh1);   // lo*hi
                }
            }
        }
        __syncthreads();
    }

    // ---- epilogue ----
    if (PACKO) {
        unsigned* Ch = p.Ch + z1 * p.cs1 + z2 * p.cs2;
        unsigned* Cl = p.Cl + z1 * p.cs1 + z2 * p.cs2;
#pragma unroll
        for (int mi = 0; mi < MT; mi++) {
            int r0 = m0 + wm * WM + mi * 16 + g;
#pragma unroll
            for (int ni = 0; ni < NTL; ni++) {
                int cw = (n0 + wn * WN + ni * 8) / 2 + t;
                unsigned h, l;
                split2(acc[mi][ni][0] * p.alpha, acc[mi][ni][1] * p.alpha, h, l);
                Ch[(long)r0 * p.ldc + cw] = h;
                Cl[(long)r0 * p.ldc + cw] = l;
                split2(acc[mi][ni][2] * p.alpha, acc[mi][ni][3] * p.alpha, h, l);
                Ch[(long)(r0 + 8) * p.ldc + cw] = h;
                Cl[(long)(r0 + 8) * p.ldc + cw] = l;
            }
        }
    } else {
        float* C = p.C + z1 * p.cs1 + z2 * p.cs2;
#pragma unroll
        for (int mi = 0; mi < MT; mi++) {
            int r0 = m0 + wm * WM + mi * 16 + g;
#pragma unroll
            for (int ni = 0; ni < NTL; ni++) {
                int col = n0 + wn * WN + ni * 8 + t * 2;
                float bx = 0.f, by = 0.f;
                if (p.bias) { bx = p.bias[col]; by = p.bias[col + 1]; }
                float2 v0, v1;
                v0.x = acc[mi][ni][0] * p.alpha + bx;
                v0.y = acc[mi][ni][1] * p.alpha + by;
                v1.x = acc[mi][ni][2] * p.alpha + bx;
                v1.y = acc[mi][ni][3] * p.alpha + by;
                *(float2*)&C[(long)r0 * p.ldc + col]       = v0;
                *(float2*)&C[(long)(r0 + 8) * p.ldc + col] = v1;
            }
        }
    }
}

// ---------------------------------------------------------------------------
// Talking-heads softmax: premix -> softmax -> postmix; writes packed bf16 attn
// ---------------------------------------------------------------------------
__global__ void __launch_bounds__(512) mix_softmax3(
    const float* __restrict__ dots,
    unsigned* __restrict__ ath, unsigned* __restrict__ atl,
    const float* __restrict__ pre_g,
    const float* __restrict__ post_g)
{
    __shared__ float s_pre[HEADS * HEADS], s_post[HEADS * HEADS];
    __shared__ float red[16][HEADS];
    __shared__ float bm[HEADS], bs[HEADS];

    const int tid = threadIdx.x;
    if (tid < HEADS * HEADS) { s_pre[tid] = pre_g[tid]; s_post[tid] = post_g[tid]; }
    __syncthreads();

    const long base   = (long)blockIdx.x * (HEADS * NJ);
    const long base_w = (long)blockIdx.x * (HEADS * NJ / 2);
    const int j0 = tid * 4;
    const int w = tid >> 5, lane = tid & 31;

    float4 mx[HEADS];
#pragma unroll
    for (int gg = 0; gg < HEADS; gg++) mx[gg] = make_float4(0.f, 0.f, 0.f, 0.f);
#pragma unroll
    for (int h = 0; h < HEADS; h++) {
        float4 r = *(const float4*)(dots + base + (long)h * NJ + j0);
#pragma unroll
        for (int gg = 0; gg < HEADS; gg++) {
            float wv = s_pre[h * HEADS + gg];
            mx[gg].x += r.x * wv;
            mx[gg].y += r.y * wv;
            mx[gg].z += r.z * wv;
            mx[gg].w += r.w * wv;
        }
    }

    float m[HEADS];
#pragma unroll
    for (int gg = 0; gg < HEADS; gg++)
        m[gg] = fmaxf(fmaxf(mx[gg].x, mx[gg].y), fmaxf(mx[gg].z, mx[gg].w));
#pragma unroll
    for (int gg = 0; gg < HEADS; gg++)
#pragma unroll
        for (int o = 16; o; o >>= 1)
            m[gg] = fmaxf(m[gg], __shfl_xor_sync(0xFFFFFFFFu, m[gg], o));
#pragma unroll
    for (int gg = 0; gg < HEADS; gg++)
        if (lane == gg) red[w][gg] = m[gg];
    __syncthreads();
    if (tid < HEADS) {
        float mm = -1e30f;
#pragma unroll
        for (int ww = 0; ww < 16; ww++) mm = fmaxf(mm, red[ww][tid]);
        bm[tid] = mm;
    }
    __syncthreads();

    float s[HEADS];
#pragma unroll
    for (int gg = 0; gg < HEADS; gg++) {
        float mm = bm[gg];
        mx[gg].x = __expf(mx[gg].x - mm);
        mx[gg].y = __expf(mx[gg].y - mm);
        mx[gg].z = __expf(mx[gg].z - mm);
        mx[gg].w = __expf(mx[gg].w - mm);
        s[gg] = (mx[gg].x + mx[gg].y) + (mx[gg].z + mx[gg].w);
    }
#pragma unroll
    for (int gg = 0; gg < HEADS; gg++)
#pragma unroll
        for (int o = 16; o; o >>= 1)
            s[gg] += __shfl_xor_sync(0xFFFFFFFFu, s[gg], o);
    __syncthreads();
#pragma unroll
    for (int gg = 0; gg < HEADS; gg++)
        if (lane == gg) red[w][gg] = s[gg];
    __syncthreads();
    if (tid < HEADS) {
        float ss = 0.f;
#pragma unroll
        for (int ww = 0; ww < 16; ww++) ss += red[ww][tid];
        bs[tid] = ss;
    }
    __syncthreads();

#pragma unroll
    for (int gg = 0; gg < HEADS; gg++) {
        float inv = 1.0f / bs[gg];
        mx[gg].x *= inv; mx[gg].y *= inv; mx[gg].z *= inv; mx[gg].w *= inv;
    }

#pragma unroll
    for (int gg = 0; gg < HEADS; gg++) {
        float4 o = make_float4(0.f, 0.f, 0.f, 0.f);
#pragma unroll
        for (int h = 0; h < HEADS; h++) {
            float wv = s_post[h * HEADS + gg];
            o.x += mx[h].x * wv;
            o.y += mx[h].y * wv;
            o.z += mx[h].z * wv;
            o.w += mx[h].w * wv;
        }
        unsigned h0, l0, h1, l1;
        split2(o.x, o.y, h0, l0);
        split2(o.z, o.w, h1, l1);
        long idx = base_w + (long)gg * (NJ / 2) + tid * 2;
        *(uint2*)&ath[idx] = make_uint2(h0, h1);
        *(uint2*)&atl[idx] = make_uint2(l0, l1);
    }
}

// ---------------------------------------------------------------------------
// Launch
// ---------------------------------------------------------------------------
#define SMEM_NN128  (2 * (2 * (128*20) + 2 * (16*132)) * 4)  // 74752
#define SMEM_BT128  (2 * (2 * (128*20) + 2 * (128*20)) * 4)  // 81920
#define SMEM_NN64   (2 * (2 * (128*20) + 2 * (16*68))  * 4)  // 58368

extern "C" void kernel_launch(void* const* d_in, const int* in_sizes, int n_in,
                              void* d_out, int out_size) {
    (void)in_sizes; (void)n_in; (void)out_size;
    const float* x        = (const float*)d_in[0];
    const float* context  = (const float*)d_in[1];
    const float* Wq       = (const float*)d_in[2];
    const float* Wkv      = (const float*)d_in[3];
    const float* mix_pre  = (const float*)d_in[4];
    const float* mix_post = (const float*)d_in[5];
    const float* Wout     = (const float*)d_in[6];
    const float* b_out    = (const float*)d_in[7];
    float* out = (float*)d_out;

    unsigned *xch, *xcl, *wqh, *wql, *wkvh, *wkvl, *wouth, *woutl;
    unsigned *qh, *ql, *kh, *kl, *vh, *vl, *ath, *atl, *aoh, *aol;
    float *kv, *dots;
    cudaGetSymbolAddress((void**)&xch, g_xch);   cudaGetSymbolAddress((void**)&xcl, g_xcl);
    cudaGetSymbolAddress((void**)&wqh, g_wqh);   cudaGetSymbolAddress((void**)&wql, g_wql);
    cudaGetSymbolAddress((void**)&wkvh, g_wkvh); cudaGetSymbolAddress((void**)&wkvl, g_wkvl);
    cudaGetSymbolAddress((void**)&wouth, g_wouth); cudaGetSymbolAddress((void**)&woutl, g_woutl);
    cudaGetSymbolAddress((void**)&qh, g_qh);     cudaGetSymbolAddress((void**)&ql, g_ql);
    cudaGetSymbolAddress((void**)&kh, g_kh);     cudaGetSymbolAddress((void**)&kl, g_kl);
    cudaGetSymbolAddress((void**)&vh, g_vh);     cudaGetSymbolAddress((void**)&vl, g_vl);
    cudaGetSymbolAddress((void**)&ath, g_ath);   cudaGetSymbolAddress((void**)&atl, g_atl);
    cudaGetSymbolAddress((void**)&aoh, g_aoh);   cudaGetSymbolAddress((void**)&aol, g_aol);
    cudaGetSymbolAddress((void**)&kv, g_kv);     cudaGetSymbolAddress((void**)&dots, g_dots);

    cudaFuncSetAttribute(bf16_gemm<128,128,32,64,false,true>,
                         cudaFuncAttributeMaxDynamicSharedMemorySize, SMEM_NN128);
    cudaFuncSetAttribute(bf16_gemm<128,128,32,64,false,false>,
                         cudaFuncAttributeMaxDynamicSharedMemorySize, SMEM_NN128);
    cudaFuncSetAttribute(bf16_gemm<128,128,32,64,true,false>,
                         cudaFuncAttributeMaxDynamicSharedMemorySize, SMEM_BT128);
    cudaFuncSetAttribute(bf16_gemm<128,64,32,32,false,true>,
                         cudaFuncAttributeMaxDynamicSharedMemorySize, SMEM_NN64);

    // ---- pack inputs ----
    pack_xc<<<3072, 256>>>(x, context, xch, xcl);
    pack_rows_g<<<288, 256>>>(Wq,   DMODEL*0 + INNER,     wqh,   wql,   INNER,     INNER/4,     (long)(DMODEL/2) * (INNER/4));
    pack_rows_g<<<576, 256>>>(Wkv,  2*INNER,              wkvh,  wkvl,  2*INNER,   2*INNER/4,   (long)(DMODEL/2) * (2*INNER/4));
    pack_rows_g<<<288, 256>>>(Wout, DMODEL,               wouth, woutl, DMODEL,    DMODEL/4,    (long)(INNER/2)  * (DMODEL/4));

    // K1: q = xc[:NQ] @ Wq  -> packed q
    {
        GP p = {};
        p.Ah = xch; p.Al = xcl; p.Bh = wqh; p.Bl = wql;
        p.Ch = qh; p.Cl = ql;
        p.K = DMODEL; p.ldaw = DMODEL/2; p.ldbw = INNER; p.ldc = INNER/2;
        p.Z2 = 1;
        p.as1 = (long)NJ * (DMODEL/2);
        p.cs1 = (long)NQ * (INNER/2);
        p.alpha = 1.0f;
        bf16_gemm<128,128,32,64,false,true>
            <<<dim3(INNER/128, NQ/128, BATCH), 256, SMEM_NN128>>>(p);
    }
    // K2: kv = xc @ Wkv  -> fp32 kv
    {
        GP p = {};
        p.Ah = xch; p.Al = xcl; p.Bh = wkvh; p.Bl = wkvl;
        p.C = kv;
        p.K = DMODEL; p.ldaw = DMODEL/2; p.ldbw = 2*INNER; p.ldc = 2*INNER;
        p.Z2 = 1;
        p.as1 = (long)NJ * (DMODEL/2);
        p.cs1 = (long)NJ * 2 * INNER;
        p.alpha = 1.0f;
        bf16_gemm<128,128,32,64,false,false>
            <<<dim3(2*INNER/128, NJ/128, BATCH), 256, SMEM_NN128>>>(p);
    }
    // pack k (cols, contiguous) and v (rows, strided)
    pack_cols_g<<<3072, 256>>>(kv,        2*INNER, kh, kl, INNER/2, INNER/8, (long)BATCH*NJ*(INNER/8));
    pack_rows_g<<<3072, 256>>>(kv + INNER, 2*INNER, vh, vl, INNER,   INNER/4, (long)BATCH*(NJ/2)*(INNER/4));

    // K3: dots = SCALE * q @ k^T  (BT, 48 batch-heads) -> fp32
    {
        GP p = {};
        p.Ah = qh; p.Al = ql; p.Bh = kh; p.Bl = kl;
        p.C = dots;
        p.K = DHEAD; p.ldaw = INNER/2; p.ldbw = INNER/2; p.ldc = HEADS*NJ;
        p.Z2 = HEADS;
        p.as1 = (long)NQ * (INNER/2); p.as2 = DHEAD/2;
        p.bs1 = (long)NJ * (INNER/2); p.bs2 = DHEAD/2;
        p.cs1 = (long)NQ * HEADS * NJ; p.cs2 = NJ;
        p.alpha = SCALE;
        bf16_gemm<128,128,32,64,true,false>
            <<<dim3(NJ/128, NQ/128, BATCH*HEADS), 256, SMEM_BT128>>>(p);
    }
    // K4: talking-heads softmax -> packed attn
    mix_softmax3<<<BATCH * NQ, 512>>>(dots, ath, atl, mix_pre, mix_post);
    // K5: ao = attn @ v  (NN, 48 batch-heads) -> packed ao
    {
        GP p = {};
        p.Ah = ath; p.Al = atl; p.Bh = vh; p.Bl = vl;
        p.Ch = aoh; p.Cl = aol;
        p.K = NJ; p.ldaw = HEADS*(NJ/2); p.ldbw = INNER; p.ldc = INNER/2;
        p.Z2 = HEADS;
        p.as1 = (long)NQ * HEADS * (NJ/2); p.as2 = NJ/2;
        p.bs1 = (long)(NJ/2) * INNER;      p.bs2 = DHEAD;
        p.cs1 = (long)NQ * (INNER/2);      p.cs2 = DHEAD/2;
        p.alpha = 1.0f;
        bf16_gemm<128,64,32,32,false,true>
            <<<dim3(1, NQ/128, BATCH*HEADS), 256, SMEM_NN64>>>(p);
    }
    // K6: out = ao @ Wout + b_out  -> fp32
    {
        GP p = {};
        p.Ah = aoh; p.Al = aol; p.Bh = wouth; p.Bl = woutl;
        p.C = out; p.bias = b_out;
        p.K = INNER; p.ldaw = INNER/2; p.ldbw = DMODEL; p.ldc = DMODEL;
        p.Z2 = 1;
        p.alpha = 1.0f;
        bf16_gemm<128,128,32,64,false,false>
            <<<dim3(DMODEL/128, (BATCH*NQ)/128, 1), 256, SMEM_NN128>>>(p);
    }
}